// round 1
// baseline (speedup 1.0000x reference)
#include <cuda_runtime.h>
#include <math.h>

#define B 16
#define T (1 << 20)
#define NTH 256
#define PER_TH 16
#define CHUNK (NTH * PER_TH)      // 4096
#define NCH (T / CHUNK)           // 256
#define STEP (1.0f / 48000.0f)
#define RISE_RATIO 0.66f
#define EPSV 1e-6f
#define PI_F 3.14159265358979f

// scratch (no device-side allocation allowed)
__device__ float  g_partials[B * NCH];
__device__ double g_offsets[B * NCH];

// ---------------- Pass 1: per-chunk sums ----------------
__global__ __launch_bounds__(NTH) void k_partials(const float* __restrict__ f0) {
    const int b = blockIdx.y, ch = blockIdx.x;
    const float4* p = reinterpret_cast<const float4*>(f0 + (size_t)b * T + (size_t)ch * CHUNK)
                      + threadIdx.x * (PER_TH / 4);
    float s = 0.f;
#pragma unroll
    for (int i = 0; i < PER_TH / 4; i++) {
        float4 v = p[i];
        s += (v.x + v.y) + (v.z + v.w);
    }
#pragma unroll
    for (int d = 16; d; d >>= 1) s += __shfl_down_sync(0xFFFFFFFFu, s, d);
    __shared__ float ws[NTH / 32];
    if ((threadIdx.x & 31) == 0) ws[threadIdx.x >> 5] = s;
    __syncthreads();
    if (threadIdx.x == 0) {
        float t = 0.f;
#pragma unroll
        for (int i = 0; i < NTH / 32; i++) t += ws[i];
        g_partials[b * NCH + ch] = t * STEP;
    }
}

// ---------------- Pass 2: per-row exclusive scan of chunk sums (fp64) ------
__global__ void k_rowscan(const float* __restrict__ phase_state,
                          float* __restrict__ out, int out_size) {
    const int b = blockIdx.x;
    if (threadIdx.x != 0) return;
    double acc = (double)phase_state[b];
    for (int ch = 0; ch < NCH; ch++) {
        g_offsets[b * NCH + ch] = acc;
        acc += (double)g_partials[b * NCH + ch];
    }
    // next_state = unwrapped final phase
    long long idx = (long long)B * T + b;
    if (idx < (long long)out_size) out[idx] = (float)acc;
}

// ---------------- Pass 3: in-block scan + Rosenberg pulse ----------------
__global__ __launch_bounds__(NTH) void k_wav(const float* __restrict__ f0,
                                             const float* __restrict__ oq,
                                             float* __restrict__ out) {
    const int b = blockIdx.y, ch = blockIdx.x;
    const size_t base = (size_t)b * T + (size_t)ch * CHUNK;
    const int lane = threadIdx.x & 31, wid = threadIdx.x >> 5;

    const float4* pf = reinterpret_cast<const float4*>(f0 + base) + threadIdx.x * (PER_TH / 4);
    const float4* po = reinterpret_cast<const float4*>(oq + base) + threadIdx.x * (PER_TH / 4);
    float4*       pw = reinterpret_cast<float4*>(out + base)       + threadIdx.x * (PER_TH / 4);

    // thread-local inclusive prefix of phase_step
    float s[PER_TH];
    float acc = 0.f;
#pragma unroll
    for (int i = 0; i < PER_TH / 4; i++) {
        float4 v = pf[i];
        acc += v.x * STEP; s[i * 4 + 0] = acc;
        acc += v.y * STEP; s[i * 4 + 1] = acc;
        acc += v.z * STEP; s[i * 4 + 2] = acc;
        acc += v.w * STEP; s[i * 4 + 3] = acc;
    }

    // block exclusive scan of thread totals
    const float tot = acc;
    float incl = tot;
#pragma unroll
    for (int d = 1; d < 32; d <<= 1) {
        float n = __shfl_up_sync(0xFFFFFFFFu, incl, d);
        if (lane >= d) incl += n;
    }
    const float wexcl = incl - tot;
    __shared__ float wsum[NTH / 32];
    __shared__ float wbase[NTH / 32];
    if (lane == 31) wsum[wid] = incl;
    __syncthreads();
    if (threadIdx.x == 0) {
        float r = 0.f;
#pragma unroll
        for (int i = 0; i < NTH / 32; i++) { wbase[i] = r; r += wsum[i]; }
    }
    __syncthreads();

    // absolute phase base for this thread (fp64 only here)
    const double based = g_offsets[b * NCH + ch] + (double)(wbase[wid] + wexcl);
    const float frac = (float)(based - floor(based));   // in [0, 1]

#pragma unroll
    for (int i = 0; i < PER_TH / 4; i++) {
        float4 q = po[i];
        float4 w;
        float* qv = &q.x;
        float* wv = &w.x;
#pragma unroll
        for (int j = 0; j < 4; j++) {
            float ph = frac + s[i * 4 + j];
            ph -= floorf(ph);                 // wrapped to [0,1)
            const float oqv = qv[j];
            const float tp = oqv * RISE_RATIO;
            const float tn = oqv - tp;
            const bool rise = ph < tp;
            const bool open = ph < oqv;
            const float arg = rise ? __fdividef(PI_F * ph, tp + EPSV)
                                   : __fdividef(PI_F * (ph - tp), 2.f * tn + EPSV);
            const float c = __cosf(arg);
            wv[j] = rise ? 0.5f - 0.5f * c : (open ? c : 0.f);
        }
        pw[i] = w;
    }
}

extern "C" void kernel_launch(void* const* d_in, const int* in_sizes, int n_in,
                              void* d_out, int out_size) {
    const float* f0 = (const float*)d_in[0];
    const float* oq = (const float*)d_in[1];
    const float* ps = (const float*)d_in[2];
    float* out = (float*)d_out;

    dim3 grid(NCH, B);
    k_partials<<<grid, NTH>>>(f0);
    k_rowscan<<<B, 32>>>(ps, out, out_size);
    k_wav<<<grid, NTH>>>(f0, oq, out);
}